// round 5
// baseline (speedup 1.0000x reference)
#include <cuda_runtime.h>
#include <cuda_bf16.h>

#define B_ 64
#define T_ 1024
#define I_ 8
#define H_ 512
#define O_ 2
#define NOISE_STD_ 0.05f
#define ALPHA_ 0.2f

#define NT_  64             // threads per CTA (2 warps)
#define UPT_ 8              // hidden units per thread
#define NP_  4              // packed f32x2 pairs per thread
#define NW_  2              // warps

#define SA_   131072.0f     // 2^17 fixed-point scale for recurrence dots
#define SO_   2097152.0f    // 2^21 fixed-point scale for output dots

typedef unsigned long long u64;

// ---- packed f32x2 helpers (Blackwell FFMA2/FADD2 pipe, PTX-only) ----
__device__ __forceinline__ u64 pack2(float x, float y) {
    u64 r; asm("mov.b64 %0, {%1, %2};" : "=l"(r) : "f"(x), "f"(y)); return r;
}
__device__ __forceinline__ void unpack2(u64 v, float& x, float& y) {
    asm("mov.b64 {%0, %1}, %2;" : "=f"(x), "=f"(y) : "l"(v));
}
__device__ __forceinline__ u64 fma2(u64 a, u64 b, u64 c) {
    u64 r; asm("fma.rn.f32x2 %0, %1, %2, %3;" : "=l"(r) : "l"(a), "l"(b), "l"(c)); return r;
}
__device__ __forceinline__ u64 mul2(u64 a, u64 b) {
    u64 r; asm("mul.rn.f32x2 %0, %1, %2;" : "=l"(r) : "l"(a), "l"(b)); return r;
}

// Single-MUFU tanh (~6e-4 rel err; net kernel rel_err ~1e-5, traj-dominated).
__device__ __forceinline__ float tanh_mufu(float x) {
    float r; asm("tanh.approx.f32 %0, %1;" : "=f"(r) : "f"(x)); return r;
}

// Warp-wide integer add-reduction (s32 redux IS supported on sm_103).
__device__ __forceinline__ int redux_add_s32(int v) {
    int r; asm("redux.sync.add.s32 %0, %1, 0xffffffff;" : "=r"(r) : "r"(v)); return r;
}

__global__ __launch_bounds__(NT_, 1)
void lowrank_rnn_kernel(const float* __restrict__ input,   // (B,T,I)
                        const float* __restrict__ noise,   // (B,T,H)
                        const float* __restrict__ wi,      // (I,H)
                        const float* __restrict__ si,      // (I,)
                        const float* __restrict__ m,       // (H,R)
                        const float* __restrict__ n,       // (H,R)
                        const float* __restrict__ wo,      // (H,O)
                        const float* __restrict__ so,      // (O,)
                        const float* __restrict__ h0,      // (H,)
                        float* __restrict__ out,           // (B,T,O)
                        float* __restrict__ traj)          // (B,T,H)
{
    __shared__ float s_in[T_ * I_];          // 32 KB: full input row for this batch
    __shared__ int4  s_red[2][NW_];          // per-warp int partials, dbl-buffered

    const int b    = blockIdx.x;
    const int tid  = threadIdx.x;
    const int warp = tid >> 5;
    const int lane = tid & 31;
    const int k0   = tid * UPT_;

    // ---- stage input into smem, coalesced float4 ----
    {
        const float4* gin  = (const float4*)(input + (size_t)b * T_ * I_);
        float4*       sin4 = (float4*)s_in;
        #pragma unroll
        for (int i = 0; i < (T_ * I_ / 4) / NT_; ++i)     // 32 iters
            sin4[tid + i * NT_] = gin[tid + i * NT_];
    }

    // ---- per-thread weights, packed into f32x2 pairs, constants folded ----
    // wif folded with si and ALPHA (projection contributes alpha*p directly)
    u64 wif2[I_][NP_];
    #pragma unroll
    for (int i = 0; i < I_; ++i) {
        const float4 w0 = *(const float4*)(wi + i * H_ + k0);
        const float4 w1 = *(const float4*)(wi + i * H_ + k0 + 4);
        const float  s  = si[i] * ALPHA_;
        wif2[i][0] = pack2(w0.x * s, w0.y * s);
        wif2[i][1] = pack2(w0.z * s, w0.w * s);
        wif2[i][2] = pack2(w1.x * s, w1.y * s);
        wif2[i][3] = pack2(w1.z * s, w1.w * s);
    }
    const float cm  = (ALPHA_ / (float)H_) / SA_;   // alpha/H and 1/Sa into m
    const float so0 = (so[0] / (float)H_) * SO_;    // 1/H and So into wo
    const float so1 = (so[1] / (float)H_) * SO_;
    u64 m0f2[NP_], m1f2[NP_], n0f2[NP_], n1f2[NP_], wo0f2[NP_], wo1f2[NP_];
    #pragma unroll
    for (int j = 0; j < NP_; ++j) {
        const int ka = k0 + 2 * j * 1 + 0;  // unit index of low half
        const int kb = ka + 1;
        m0f2[j]  = pack2(m[ka * 2 + 0] * cm,  m[kb * 2 + 0] * cm);
        m1f2[j]  = pack2(m[ka * 2 + 1] * cm,  m[kb * 2 + 1] * cm);
        n0f2[j]  = pack2(n[ka * 2 + 0] * SA_, n[kb * 2 + 0] * SA_);
        n1f2[j]  = pack2(n[ka * 2 + 1] * SA_, n[kb * 2 + 1] * SA_);
        wo0f2[j] = pack2(wo[ka * 2 + 0] * so0, wo[kb * 2 + 0] * so0);
        wo1f2[j] = pack2(wo[ka * 2 + 1] * so1, wo[kb * 2 + 1] * so1);
    }
    const u64 C005 = pack2(NOISE_STD_, NOISE_STD_);
    const u64 C08  = pack2(1.0f - ALPHA_, 1.0f - ALPHA_);

    // Wait: pairs must be CONSECUTIVE units (ka = k0+2j, kb = k0+2j+1) — fixed above.

    u64 h2[NP_];
    {
        const float4 ha = *(const float4*)(h0 + k0);
        const float4 hb = *(const float4*)(h0 + k0 + 4);
        h2[0] = pack2(ha.x, ha.y); h2[1] = pack2(ha.z, ha.w);
        h2[2] = pack2(hb.x, hb.y); h2[3] = pack2(hb.z, hb.w);
    }

    const float* nz_base   = noise + (size_t)b * T_ * H_ + k0;
    float*       traj_base = traj  + (size_t)b * T_ * H_ + k0;
    float*       out_base  = out   + (size_t)b * T_ * O_;

    // ---- noise prefetch ring, depth 4 (2 float4 per step) ----
    float4 ring[8];
    #pragma unroll
    for (int j = 0; j < 4; ++j) {
        ring[2 * j + 0] = *(const float4*)(nz_base + (size_t)j * H_);
        ring[2 * j + 1] = *(const float4*)(nz_base + (size_t)j * H_ + 4);
    }

    // ---- pre-loop: a = n^T r_0 into buffer 1 ----
    u64 A0s, A1s;
    {
        u64 acc0 = 0, acc1 = 0;
        bool first = true;
        #pragma unroll
        for (int j = 0; j < NP_; ++j) {
            float x, y; unpack2(h2[j], x, y);
            const u64 r2 = pack2(tanh_mufu(x), tanh_mufu(y));
            if (first) { acc0 = mul2(r2, n0f2[j]); acc1 = mul2(r2, n1f2[j]); first = false; }
            else       { acc0 = fma2(r2, n0f2[j], acc0); acc1 = fma2(r2, n1f2[j], acc1); }
        }
        float a0x, a0y, a1x, a1y;
        unpack2(acc0, a0x, a0y); unpack2(acc1, a1x, a1y);
        const int ia0 = redux_add_s32(__float2int_rn(a0x + a0y));
        const int ia1 = redux_add_s32(__float2int_rn(a1x + a1y));
        if (lane == 0) s_red[1][warp] = make_int4(ia0, ia1, 0, 0);
        __syncthreads();                 // also covers s_in staging
        const int4 v0 = s_red[1][0];
        const int4 v1 = s_red[1][1];
        const float a0 = (float)(v0.x + v1.x);
        const float a1 = (float)(v0.y + v1.y);
        A0s = pack2(a0, a0); A1s = pack2(a1, a1);
    }

    // ---- main scan ----
    #pragma unroll 4
    for (int t = 0; t < T_; ++t) {
        const int rj = (t & 3) * 2;
        const float4 nzA = ring[rj + 0];
        const float4 nzB = ring[rj + 1];
        int tp = t + 4; if (tp > T_ - 1) tp = T_ - 1;             // clamp tail
        ring[rj + 0] = *(const float4*)(nz_base + (size_t)tp * H_);
        ring[rj + 1] = *(const float4*)(nz_base + (size_t)tp * H_ + 4);

        // input projection (alpha folded): p2[j] for 4 pairs, packed
        const float4 i0 = *(const float4*)(s_in + t * I_);
        const float4 i1 = *(const float4*)(s_in + t * I_ + 4);
        const u64 xs[I_] = { pack2(i0.x, i0.x), pack2(i0.y, i0.y),
                             pack2(i0.z, i0.z), pack2(i0.w, i0.w),
                             pack2(i1.x, i1.x), pack2(i1.y, i1.y),
                             pack2(i1.z, i1.z), pack2(i1.w, i1.w) };
        u64 p2[NP_];
        #pragma unroll
        for (int j = 0; j < NP_; ++j) {
            u64 pp = mul2(xs[0], wif2[0][j]);
            #pragma unroll
            for (int i = 1; i < I_; ++i) pp = fma2(xs[i], wif2[i][j], pp);
            p2[j] = pp;
        }
        const u64 nz2[NP_] = { pack2(nzA.x, nzA.y), pack2(nzA.z, nzA.w),
                               pack2(nzB.x, nzB.y), pack2(nzB.z, nzB.w) };

        // h' = 0.8h + 0.05nz + alpha*p + a0*m0 + a1*m1 ; r' = tanh(h')
        float hs[UPT_];
        u64 r2[NP_];
        u64 aa0 = 0, aa1 = 0, oo0 = 0, oo1 = 0;
        #pragma unroll
        for (int j = 0; j < NP_; ++j) {
            u64 hb = fma2(nz2[j], C005, p2[j]);      // off critical path
            hb     = fma2(h2[j], C08, hb);           // off critical path
            u64 hx = fma2(A0s, m0f2[j], hb);         // crit path: 2 packed FMA
            hx     = fma2(A1s, m1f2[j], hx);
            h2[j] = hx;
            float x, y; unpack2(hx, x, y);
            hs[2 * j] = x; hs[2 * j + 1] = y;
            r2[j] = pack2(tanh_mufu(x), tanh_mufu(y));
            if (j == 0) {
                aa0 = mul2(r2[j], n0f2[j]);  aa1 = mul2(r2[j], n1f2[j]);
                oo0 = mul2(r2[j], wo0f2[j]); oo1 = mul2(r2[j], wo1f2[j]);
            } else {
                aa0 = fma2(r2[j], n0f2[j], aa0);  aa1 = fma2(r2[j], n1f2[j], aa1);
                oo0 = fma2(r2[j], wo0f2[j], oo0); oo1 = fma2(r2[j], wo1f2[j], oo1);
            }
        }

        // traj[t] = h_{t+1}, 2x STG.128
        *(float4*)(traj_base + (size_t)t * H_)     = make_float4(hs[0], hs[1], hs[2], hs[3]);
        *(float4*)(traj_base + (size_t)t * H_ + 4) = make_float4(hs[4], hs[5], hs[6], hs[7]);

        // horizontal + fixed-point warp reduction (a-pair first: on crit path)
        float ax, ay; int ia0, ia1, io0, io1;
        unpack2(aa0, ax, ay); ia0 = redux_add_s32(__float2int_rn(ax + ay));
        unpack2(aa1, ax, ay); ia1 = redux_add_s32(__float2int_rn(ax + ay));
        unpack2(oo0, ax, ay); io0 = redux_add_s32(__float2int_rn(ax + ay));
        unpack2(oo1, ax, ay); io1 = redux_add_s32(__float2int_rn(ax + ay));

        const int buf = t & 1;
        if (lane == 0) s_red[buf][warp] = make_int4(ia0, ia1, io0, io1);
        __syncthreads();                  // one bar per step (double-buffered)

        const int4 v0 = s_red[buf][0];
        const int4 v1 = s_red[buf][1];
        const float a0 = (float)(v0.x + v1.x);
        const float a1 = (float)(v0.y + v1.y);
        A0s = pack2(a0, a0); A1s = pack2(a1, a1);

        if (tid == 0) {
            const float o0 = (float)(v0.z + v1.z) * (1.0f / SO_);
            const float o1 = (float)(v0.w + v1.w) * (1.0f / SO_);
            *(float2*)(out_base + (size_t)t * O_) = make_float2(o0, o1);
        }
    }
}

extern "C" void kernel_launch(void* const* d_in, const int* in_sizes, int n_in,
                              void* d_out, int out_size) {
    const float* input = (const float*)d_in[0];
    const float* noise = (const float*)d_in[1];
    const float* wi    = (const float*)d_in[2];
    const float* si    = (const float*)d_in[3];
    const float* m     = (const float*)d_in[4];
    const float* n     = (const float*)d_in[5];
    const float* wo    = (const float*)d_in[6];
    const float* so    = (const float*)d_in[7];
    const float* h0    = (const float*)d_in[8];

    float* out  = (float*)d_out;                         // (B,T,O) first
    float* traj = (float*)d_out + (size_t)B_ * T_ * O_;  // then (B,T,H)

    lowrank_rnn_kernel<<<B_, NT_>>>(input, noise, wi, si, m, n, wo, so, h0,
                                    out, traj);
}

// round 6
// speedup vs baseline: 1.1015x; 1.1015x over previous
#include <cuda_runtime.h>
#include <cuda_bf16.h>

#define B_ 64
#define T_ 1024
#define I_ 8
#define H_ 512
#define O_ 2
#define NOISE_STD_ 0.05f
#define ALPHA_ 0.2f

#define NT_  128            // 4 warps (best measured config)
#define UPT_ 4              // hidden units per thread
#define NW_  4

#define SA_      8192.0f    // 2^13 fixed-point scale for recurrence dots
#define SO_      2097152.0f // 2^21 fixed-point scale for output dots
#define MAGIC_F  12582912.0f       // 2^23 + 2^22 : round-to-int bias
// Sum of 4 warp-sums, each = 32*0x4B400000 + Si (mod 2^32) = 0x68000000 + Si.
// Total = 0xA0000000 + S. Re-bias to float: u = S + 0x4B400000 = total + 0xAB400000.
#define REBIAS_I ((int)0xAB400000u)

// Single-MUFU tanh (~6e-4 rel err; net kernel rel_err ~1e-5, traj-dominated).
__device__ __forceinline__ float tanh_mufu(float x) {
    float r; asm("tanh.approx.f32 %0, %1;" : "=f"(r) : "f"(x)); return r;
}

// Warp-wide integer add-reduction (s32 redux IS supported on sm_103).
__device__ __forceinline__ int redux_add_s32(int v) {
    int r; asm("redux.sync.add.s32 %0, %1, 0xffffffff;" : "=r"(r) : "r"(v)); return r;
}

__global__ __launch_bounds__(NT_, 1)
void lowrank_rnn_kernel(const float* __restrict__ input,   // (B,T,I)
                        const float* __restrict__ noise,   // (B,T,H)
                        const float* __restrict__ wi,      // (I,H)
                        const float* __restrict__ si,      // (I,)
                        const float* __restrict__ m,       // (H,R)
                        const float* __restrict__ n,       // (H,R)
                        const float* __restrict__ wo,      // (H,O)
                        const float* __restrict__ so,      // (O,)
                        const float* __restrict__ h0,      // (H,)
                        float* __restrict__ out,           // (B,T,O)
                        float* __restrict__ traj)          // (B,T,H)
{
    __shared__ float s_in[T_ * I_];          // 32 KB: full input row for this batch
    __shared__ int2  s_a[4][NW_];            // biased a-partials, 4-slot ring (t&3)
    __shared__ int2  s_o[4][NW_];            // o-partials, 4-slot ring

    const int b    = blockIdx.x;
    const int tid  = threadIdx.x;
    const int warp = tid >> 5;
    const int lane = tid & 31;
    const int k0   = tid * UPT_;

    // ---- stage input into smem, coalesced float4 ----
    {
        const float4* gin  = (const float4*)(input + (size_t)b * T_ * I_);
        float4*       sin4 = (float4*)s_in;
        #pragma unroll
        for (int i = 0; i < (T_ * I_ / 4) / NT_; ++i)     // 16 iters
            sin4[tid + i * NT_] = gin[tid + i * NT_];
    }

    // ---- per-thread weights (all constants folded) ----
    // wif folded with si*ALPHA => projection directly contributes alpha*p.
    float wif[I_][UPT_];
    #pragma unroll
    for (int i = 0; i < I_; ++i) {
        const float4 w = *(const float4*)(wi + i * H_ + k0);
        const float  s = si[i] * ALPHA_;
        wif[i][0] = w.x * s; wif[i][1] = w.y * s;
        wif[i][2] = w.z * s; wif[i][3] = w.w * s;
    }
    const float cm  = (ALPHA_ / (float)H_) / SA_;   // alpha/H and 1/Sa folded into m
    const float so0 = (so[0] / (float)H_) * SO_;    // 1/H and So folded into wo
    const float so1 = (so[1] / (float)H_) * SO_;
    float m0f[UPT_], m1f[UPT_], n0f[UPT_], n1f[UPT_], wo0f[UPT_], wo1f[UPT_];
    float negmc[UPT_];   // -(MAGIC_F)*(m0f+m1f): cancels the bias in a0b,a1b
    #pragma unroll
    for (int j = 0; j < UPT_; ++j) {
        const int k = k0 + j;
        m0f[j]  = m[k * 2 + 0] * cm;        m1f[j]  = m[k * 2 + 1] * cm;
        n0f[j]  = n[k * 2 + 0] * SA_;       n1f[j]  = n[k * 2 + 1] * SA_;
        wo0f[j] = wo[k * 2 + 0] * so0;      wo1f[j] = wo[k * 2 + 1] * so1;
        negmc[j] = -MAGIC_F * (m0f[j] + m1f[j]);
    }

    float h[UPT_];
    {
        const float4 hh = *(const float4*)(h0 + k0);
        h[0] = hh.x; h[1] = hh.y; h[2] = hh.z; h[3] = hh.w;
    }

    const float* nz_base   = noise + (size_t)b * T_ * H_ + k0;
    float*       traj_base = traj  + (size_t)b * T_ * H_ + k0;
    float*       out_base  = out   + (size_t)b * T_ * O_;

    // ---- noise prefetch ring, depth 4 ----
    float4 ring[4];
    #pragma unroll
    for (int j = 0; j < 4; ++j)
        ring[j] = *(const float4*)(nz_base + (size_t)j * H_);

    // ---- prologue: biased a(0) from r_init = tanh(h0), and hb(0) ----
    float A0b, A1b;       // biased recurrence dots (include +MAGIC_F each)
    float hb[UPT_];       // hb(t) = 0.8h + 0.05nz + alpha*p - MAGIC*(m0+m1)
    {
        float pa0 = 0.0f, pa1 = 0.0f;
        #pragma unroll
        for (int u = 0; u < UPT_; ++u) {
            const float r = tanh_mufu(h[u]);
            pa0 = fmaf(r, n0f[u], pa0);
            pa1 = fmaf(r, n1f[u], pa1);
        }
        const int W0 = redux_add_s32(__float_as_int(pa0 + MAGIC_F));
        const int W1 = redux_add_s32(__float_as_int(pa1 + MAGIC_F));
        if (lane == 0) s_a[3][warp] = make_int2(W0, W1);

        // hb(0): projection with negmc folded into accumulator init
        const float4 i0 = *(const float4*)(s_in + 0 * I_);      // careful: staging not
        // NOTE: s_in not yet synced; compute projection AFTER the barrier below.
        (void)i0;
        __syncthreads();   // covers s_in staging + prologue partials

        const int2 v0 = s_a[3][0], v1 = s_a[3][1], v2 = s_a[3][2], v3 = s_a[3][3];
        A0b = __int_as_float(((v0.x + v1.x) + (v2.x + v3.x)) + REBIAS_I);
        A1b = __int_as_float(((v0.y + v1.y) + (v2.y + v3.y)) + REBIAS_I);

        const float4 j0 = *(const float4*)(s_in + 0);
        const float4 j1 = *(const float4*)(s_in + 4);
        const float4 nz = ring[0];
        const float nza[UPT_] = {nz.x, nz.y, nz.z, nz.w};
        #pragma unroll
        for (int u = 0; u < UPT_; ++u) {
            float pp = fmaf(j0.x, wif[0][u], negmc[u]);
            pp = fmaf(j0.y, wif[1][u], pp);
            pp = fmaf(j0.z, wif[2][u], pp);
            pp = fmaf(j0.w, wif[3][u], pp);
            pp = fmaf(j1.x, wif[4][u], pp);
            pp = fmaf(j1.y, wif[5][u], pp);
            pp = fmaf(j1.z, wif[6][u], pp);
            pp = fmaf(j1.w, wif[7][u], pp);
            pp = fmaf(NOISE_STD_, nza[u], pp);
            hb[u] = fmaf(1.0f - ALPHA_, h[u], pp);
        }
    }

    // ---- main scan ----
    #pragma unroll 4
    for (int t = 0; t < T_; ++t) {
        const int buf = t & 3;

        // ======== CRITICAL PATH ========
        // hx = hb + a0b*m0 + a1b*m1   (bias cancelled by negmc inside hb)
        float hx[UPT_], r[UPT_];
        #pragma unroll
        for (int u = 0; u < UPT_; ++u) {
            float v = fmaf(A0b, m0f[u], hb[u]);
            v       = fmaf(A1b, m1f[u], v);
            hx[u] = v;
            r[u]  = tanh_mufu(v);
        }
        // a-dots, 2-accumulator tree
        float pa0 = fmaf(r[1], n0f[1], r[0] * n0f[0]);
        float pa0b = fmaf(r[3], n0f[3], r[2] * n0f[2]);
        float pa1 = fmaf(r[1], n1f[1], r[0] * n1f[0]);
        float pa1b = fmaf(r[3], n1f[3], r[2] * n1f[2]);
        const int W0 = redux_add_s32(__float_as_int((pa0 + pa0b) + MAGIC_F));
        const int W1 = redux_add_s32(__float_as_int((pa1 + pa1b) + MAGIC_F));
        if (lane == 0) s_a[buf][warp] = make_int2(W0, W1);

        // ======== SHADOW (overlaps REDUX/barrier) ========
        // o-dots (deferred consumption at t+1)
        {
            float po0 = fmaf(r[1], wo0f[1], r[0] * wo0f[0]);
            float po0b = fmaf(r[3], wo0f[3], r[2] * wo0f[2]);
            float po1 = fmaf(r[1], wo1f[1], r[0] * wo1f[0]);
            float po1b = fmaf(r[3], wo1f[3], r[2] * wo1f[2]);
            const int U0 = redux_add_s32(__float2int_rn(po0 + po0b));
            const int U1 = redux_add_s32(__float2int_rn(po1 + po1b));
            if (lane == 0) s_o[buf][warp] = make_int2(U0, U1);
        }
        // traj[t] = h_{t+1}
        *(float4*)(traj_base + (size_t)t * H_) = make_float4(hx[0], hx[1], hx[2], hx[3]);
        // noise prefetch t+4
        {
            int tp = t + 4; if (tp > T_ - 1) tp = T_ - 1;
            ring[buf] = *(const float4*)(nz_base + (size_t)tp * H_);
        }
        // hb(t+1): projection + noise + 0.8*hx, with negmc folded in
        {
            const int tn = (t + 1 < T_) ? t + 1 : t;
            const float4 j0 = *(const float4*)(s_in + tn * I_);
            const float4 j1 = *(const float4*)(s_in + tn * I_ + 4);
            const float4 nz = ring[(t + 1) & 3];
            const float nza[UPT_] = {nz.x, nz.y, nz.z, nz.w};
            #pragma unroll
            for (int u = 0; u < UPT_; ++u) {
                float pp = fmaf(j0.x, wif[0][u], negmc[u]);
                pp = fmaf(j0.y, wif[1][u], pp);
                pp = fmaf(j0.z, wif[2][u], pp);
                pp = fmaf(j0.w, wif[3][u], pp);
                pp = fmaf(j1.x, wif[4][u], pp);
                pp = fmaf(j1.y, wif[5][u], pp);
                pp = fmaf(j1.z, wif[6][u], pp);
                pp = fmaf(j1.w, wif[7][u], pp);
                pp = fmaf(NOISE_STD_, nza[u], pp);
                hb[u] = fmaf(1.0f - ALPHA_, hx[u], pp);
            }
        }

        __syncthreads();   // one bar per step

        // combine a-partials (magic re-bias, no I2F)
        {
            const int2 v0 = s_a[buf][0], v1 = s_a[buf][1],
                       v2 = s_a[buf][2], v3 = s_a[buf][3];
            A0b = __int_as_float(((v0.x + v1.x) + (v2.x + v3.x)) + REBIAS_I);
            A1b = __int_as_float(((v0.y + v1.y) + (v2.y + v3.y)) + REBIAS_I);
        }

        // out[t-1] from previous slot's o-partials (off critical path)
        if (tid == 0 && t > 0) {
            const int pb = (t - 1) & 3;
            const int2 v0 = s_o[pb][0], v1 = s_o[pb][1],
                       v2 = s_o[pb][2], v3 = s_o[pb][3];
            const float o0 = (float)((v0.x + v1.x) + (v2.x + v3.x)) * (1.0f / SO_);
            const float o1 = (float)((v0.y + v1.y) + (v2.y + v3.y)) * (1.0f / SO_);
            *(float2*)(out_base + (size_t)(t - 1) * O_) = make_float2(o0, o1);
        }
    }

    // epilogue: out[T-1] (slot (T-1)&3 still valid; last bar covered its STS)
    if (tid == 0) {
        const int pb = (T_ - 1) & 3;
        const int2 v0 = s_o[pb][0], v1 = s_o[pb][1],
                   v2 = s_o[pb][2], v3 = s_o[pb][3];
        const float o0 = (float)((v0.x + v1.x) + (v2.x + v3.x)) * (1.0f / SO_);
        const float o1 = (float)((v0.y + v1.y) + (v2.y + v3.y)) * (1.0f / SO_);
        *(float2*)(out_base + (size_t)(T_ - 1) * O_) = make_float2(o0, o1);
    }
}

extern "C" void kernel_launch(void* const* d_in, const int* in_sizes, int n_in,
                              void* d_out, int out_size) {
    const float* input = (const float*)d_in[0];
    const float* noise = (const float*)d_in[1];
    const float* wi    = (const float*)d_in[2];
    const float* si    = (const float*)d_in[3];
    const float* m     = (const float*)d_in[4];
    const float* n     = (const float*)d_in[5];
    const float* wo    = (const float*)d_in[6];
    const float* so    = (const float*)d_in[7];
    const float* h0    = (const float*)d_in[8];

    float* out  = (float*)d_out;                         // (B,T,O) first
    float* traj = (float*)d_out + (size_t)B_ * T_ * O_;  // then (B,T,H)

    lowrank_rnn_kernel<<<B_, NT_>>>(input, noise, wi, si, m, n, wo, so, h0,
                                    out, traj);
}